// round 5
// baseline (speedup 1.0000x reference)
#include <cuda_runtime.h>
#include <math.h>

#define D       256
#define BATCH   128
#define SEQ     1024
#define ROWS    (BATCH*SEQ)          // 131072
#define NCHUNK  8
#define GBLOCKS 1024                 // 8 warps each
#define NWARPS  8
#define THREADS 256
#define RPW     (ROWS/(GBLOCKS*NWARPS))   // 16 rows per warp

// ---------------- scratch (device globals; no allocation) ----------------
__device__ __align__(16) float g_part1[BATCH*NCHUNK*D];
__device__ __align__(16) float g_c1[BATCH*D];
__device__ __align__(16) float g_mean[D];
__device__ __align__(16) float g_psum[GBLOCKS*D];
__device__ __align__(16) float g_psq[GBLOCKS*D];
__device__ __align__(16) float g_scale[D];
__device__ __align__(16) float g_sm[D];           // scale * mean
__device__ __align__(16) float4 g_rowsc[ROWS];    // per-row (fac, fac*alpha, coef, 0)

// ---------------- helpers ----------------
__device__ __forceinline__ float wsum(float v) {
    #pragma unroll
    for (int o = 16; o > 0; o >>= 1) v += __shfl_xor_sync(0xffffffffu, v, o);
    return v;
}
__device__ __forceinline__ float block_sum_bcast(float v, float* sh) {
    v = wsum(v);
    int w = threadIdx.x >> 5;
    if ((threadIdx.x & 31) == 0) sh[w] = v;
    __syncthreads();
    if (threadIdx.x < 8) {
        float t = sh[threadIdx.x];
        #pragma unroll
        for (int o = 4; o > 0; o >>= 1) t += __shfl_xor_sync(0xffu, t, o);
        if (threadIdx.x == 0) sh[0] = t;
    }
    __syncthreads();
    float r = sh[0];
    __syncthreads();
    return r;
}
// 16-lane-group butterfly (xor offsets stay within each half-warp group)
__device__ __forceinline__ float gsum16(float v) {
    #pragma unroll
    for (int o = 8; o > 0; o >>= 1) v += __shfl_xor_sync(0xffffffffu, v, o);
    return v;
}
__device__ __forceinline__ void gsum16_2(float& a, float& b) {
    #pragma unroll
    for (int o = 8; o > 0; o >>= 1) {
        a += __shfl_xor_sync(0xffffffffu, a, o);
        b += __shfl_xor_sync(0xffffffffu, b, o);
    }
}

// ---------------- kernel 1: partial sums over seq chunks ----------------
__global__ void __launch_bounds__(THREADS) k_sum_seq(const float* __restrict__ x) {
    int blk = blockIdx.x;
    int d = threadIdx.x;
    const float* p = x + (size_t)blk * 128 * D + d;
    float a0 = 0.f, a1 = 0.f, a2 = 0.f, a3 = 0.f;
    #pragma unroll 8
    for (int s = 0; s < 128; s += 4) {
        a0 += p[(size_t)(s + 0) * D];
        a1 += p[(size_t)(s + 1) * D];
        a2 += p[(size_t)(s + 2) * D];
        a3 += p[(size_t)(s + 3) * D];
    }
    g_part1[blk * D + d] = (a0 + a1) + (a2 + a3);
}

// ---------------- kernel 2: per-batch centroid ----------------
__global__ void __launch_bounds__(THREADS) k_centroid_b() {
    __shared__ float sh[8];
    int b = blockIdx.x, d = threadIdx.x;
    float s = 0.f;
    #pragma unroll
    for (int c = 0; c < NCHUNK; c++) s += g_part1[(b * NCHUNK + c) * D + d];
    float avg = s * (1.0f / SEQ);
    float contrib = (d == 0) ? -avg * avg : avg * avg;
    float lin = block_sum_bcast(contrib, sh);
    float denom = sqrtf(fmaxf(fabsf(lin), 1e-8f));
    g_c1[b * D + d] = avg / denom;
}

// ---------------- kernel 3: centroid over batch -> mean ----------------
__global__ void __launch_bounds__(THREADS) k_centroid_mean() {
    __shared__ float sh[8];
    int d = threadIdx.x;
    float s = 0.f;
    #pragma unroll 8
    for (int b = 0; b < BATCH; b++) s += g_c1[b * D + d];
    float avg = s * (1.0f / BATCH);
    float contrib = (d == 0) ? -avg * avg : avg * avg;
    float lin = block_sum_bcast(contrib, sh);
    float denom = sqrtf(fmaxf(fabsf(lin), 1e-8f));
    g_mean[d] = avg / denom;
}

// ---------------- kernel 4: pass B — 16-lane groups, 2 rows / iteration ----------------
__global__ void __launch_bounds__(THREADS) k_stats(const float* __restrict__ x) {
    __shared__ __align__(16) float sh_s[2 * NWARPS * D]; // 16 virtual warps
    __shared__ __align__(16) float sh_q[2 * NWARPS * D];
    const int lane = threadIdx.x & 31, warp = threadIdx.x >> 5;
    const int p = lane & 15, g = lane >> 4;
    const int gsrc = lane & 16;                 // p==0 lane of own group
    const int gw = blockIdx.x * NWARPS + warp;
    const int base = gw * RPW;
    const float4* X = (const float4*)x;

    float4 mk[4];
    #pragma unroll
    for (int k = 0; k < 4; k++) mk[k] = ((const float4*)g_mean)[p + 16 * k];
    const float mean0 = g_mean[0];
    const float inv1pm0 = 1.0f / (1.0f + mean0);

    float4 s[4], q[4];
    #pragma unroll
    for (int k = 0; k < 4; k++) { s[k] = make_float4(0,0,0,0); q[k] = make_float4(0,0,0,0); }

    #pragma unroll 2
    for (int i = 0; i < RPW; i += 2) {
        const int row = base + i + g;
        float4 xk[4];
        #pragma unroll
        for (int k = 0; k < 4; k++) xk[k] = X[(size_t)row * 64 + p + 16 * k];

        // Euclid dot of lane's 16 elems, with Lorentz sign fix pre-applied on p==0
        float dpar = 0.f;
        #pragma unroll
        for (int k = 0; k < 4; k++)
            dpar += xk[k].x*mk[k].x + xk[k].y*mk[k].y + xk[k].z*mk[k].z + xk[k].w*mk[k].w;
        if (p == 0) dpar -= 2.0f * mean0 * xk[0].x;     // -> group sum = linner(m, x)
        float lin = gsum16(dpar);

        float alpha = fmaxf(-lin, 1.0f + 1e-7f);
        float fac = acoshf(alpha) / sqrtf(alpha * alpha - 1.0f);
        float fa = fac * alpha;

        // t0 = fac*(x0 - alpha*m0); x0 broadcast within group (1 shfl)
        float x0b = __shfl_sync(0xffffffffu, xk[0].x, gsrc);
        float t0 = fac * (x0b - alpha * mean0);
        float coef = t0 * inv1pm0;
        float w = fa + coef;                             // folds ma = m + e0

        if (p == 0) g_rowsc[row] = make_float4(fac, fa, coef, 0.f);

        #pragma unroll
        for (int k = 0; k < 4; k++) {
            float4 t;
            t.x = fac * xk[k].x - w * mk[k].x;
            t.y = fac * xk[k].y - w * mk[k].y;
            t.z = fac * xk[k].z - w * mk[k].z;
            t.w = fac * xk[k].w - w * mk[k].w;
            if (k == 0 && p == 0) t.x -= coef;           // e0 correction (feature 0)
            s[k].x += t.x; s[k].y += t.y; s[k].z += t.z; s[k].w += t.w;
            q[k].x += t.x*t.x; q[k].y += t.y*t.y; q[k].z += t.z*t.z; q[k].w += t.w*t.w;
        }
    }

    const int vw = warp * 2 + g;                          // 16 virtual warps
    #pragma unroll
    for (int k = 0; k < 4; k++) {
        ((float4*)sh_s)[vw * 64 + p + 16 * k] = s[k];
        ((float4*)sh_q)[vw * 64 + p + 16 * k] = q[k];
    }
    __syncthreads();
    int d = threadIdx.x;
    float ts = 0.f, tq = 0.f;
    #pragma unroll
    for (int v = 0; v < 16; v++) { ts += sh_s[v * D + d]; tq += sh_q[v * D + d]; }
    g_psum[blockIdx.x * D + d] = ts;
    g_psq[blockIdx.x * D + d] = tq;
}

// ---------------- kernel 5: variance -> scale (+ scale*mean) ----------------
__global__ void __launch_bounds__(THREADS) k_var(const float* __restrict__ gamma) {
    __shared__ float sh[8];
    const int d = blockIdx.x, t = threadIdx.x;
    float s = 0.f, q = 0.f;
    #pragma unroll
    for (int g = t; g < GBLOCKS; g += THREADS) { s += g_psum[g * D + d]; q += g_psq[g * D + d]; }
    float S_ = block_sum_bcast(s, sh);
    float Q_ = block_sum_bcast(q, sh);
    if (t == 0) {
        const float invN = 1.0f / (float)ROWS;
        float mu = S_ * invN;
        float var = Q_ * invN - mu * mu;
        float sc = gamma[0] / sqrtf(var + 1e-5f);
        g_scale[d] = sc;
        g_sm[d] = sc * g_mean[d];
    }
}

// ---------------- kernel 6: pass C — 16-lane groups, 1 reduction round ----------------
__global__ void __launch_bounds__(THREADS) k_final(const float* __restrict__ x,
                                                   const float* __restrict__ beta,
                                                   float* __restrict__ out) {
    __shared__ __align__(16) float sh_bt[D];              // beta staged (saves 16 regs)
    const int lane = threadIdx.x & 31, warp = threadIdx.x >> 5;
    const int p = lane & 15, g = lane >> 4;
    const int gsrc = lane & 16;
    const int gw = blockIdx.x * NWARPS + warp;
    const int base = gw * RPW;
    const float4* X = (const float4*)x;
    float4* O = (float4*)out;

    if (threadIdx.x < D) sh_bt[threadIdx.x] = beta[threadIdx.x];
    __syncthreads();

    float4 sck[4], smk[4];
    #pragma unroll
    for (int k = 0; k < 4; k++) {
        sck[k] = ((const float4*)g_scale)[p + 16 * k];
        smk[k] = ((const float4*)g_sm)[p + 16 * k];
    }
    const float sc0 = g_scale[0];
    const float beta0 = beta[0];
    const float inv1pb0 = 1.0f / (1.0f + beta0);

    #pragma unroll 2
    for (int i = 0; i < RPW; i += 2) {
        const int row = base + i + g;
        float4 rs = g_rowsc[row];                         // (fac, fa, coef)
        const float fac = rs.x, w = rs.y + rs.z, coef = rs.z;

        float4 tk[4];
        #pragma unroll
        for (int k = 0; k < 4; k++) {
            float4 xv = X[(size_t)row * 64 + p + 16 * k];
            // t' = scale*(fac*x - w*m - coef*e0) = fac*(scale*x) - w*(scale*m) - coef*scale0*e0
            tk[k].x = fac * (sck[k].x * xv.x) - w * smk[k].x;
            tk[k].y = fac * (sck[k].y * xv.y) - w * smk[k].y;
            tk[k].z = fac * (sck[k].z * xv.z) - w * smk[k].z;
            tk[k].w = fac * (sck[k].w * xv.w) - w * smk[k].w;
        }
        if (p == 0) tk[0].x -= coef * sc0;

        // one reduction round: db = linner(beta, t') (sign pre-fixed), tt = sum t'^2
        float db = 0.f, tt = 0.f;
        #pragma unroll
        for (int k = 0; k < 4; k++) {
            float4 bv = ((const float4*)sh_bt)[p + 16 * k];
            db += tk[k].x*bv.x + tk[k].y*bv.y + tk[k].z*bv.z + tk[k].w*bv.w;
            tt += tk[k].x*tk[k].x + tk[k].y*tk[k].y + tk[k].z*tk[k].z + tk[k].w*tk[k].w;
        }
        if (p == 0) db -= 2.0f * beta0 * tk[0].x;
        gsum16_2(db, tt);

        float t0 = __shfl_sync(0xffffffffu, tk[0].x, gsrc);
        float c2 = db * inv1pb0;
        float uu = tt - 2.0f * t0 * t0 - 2.0f * c2 * t0;  // linner(u,u)
        float n = sqrtf(fmaxf(uu, 1e-7f));
        float ep = expf(n), em = 1.0f / ep;
        float ch = 0.5f * (ep + em);
        float shn = 0.5f * (ep - em) / n;
        float A = ch + shn * c2;                          // o = A*beta + shn*t' + shn*c2*e0

        #pragma unroll
        for (int k = 0; k < 4; k++) {
            float4 bv = ((const float4*)sh_bt)[p + 16 * k];
            float4 o;
            o.x = A * bv.x + shn * tk[k].x;
            o.y = A * bv.y + shn * tk[k].y;
            o.z = A * bv.z + shn * tk[k].z;
            o.w = A * bv.w + shn * tk[k].w;
            if (k == 0 && p == 0) o.x += shn * c2;        // e0 term
            O[(size_t)row * 64 + p + 16 * k] = o;
        }
    }
}

// ---------------- launch ----------------
extern "C" void kernel_launch(void* const* d_in, const int* in_sizes, int n_in,
                              void* d_out, int out_size) {
    const float* x     = (const float*)d_in[0];
    const float* beta  = (const float*)d_in[1];
    const float* gamma = (const float*)d_in[2];
    float* out = (float*)d_out;
    (void)in_sizes; (void)n_in; (void)out_size;

    k_sum_seq<<<BATCH * NCHUNK, THREADS>>>(x);
    k_centroid_b<<<BATCH, THREADS>>>();
    k_centroid_mean<<<1, THREADS>>>();
    k_stats<<<GBLOCKS, THREADS>>>(x);
    k_var<<<D, THREADS>>>(gamma);
    k_final<<<GBLOCKS, THREADS>>>(x, beta, out);
}